// round 15
// baseline (speedup 1.0000x reference)
#include <cuda_runtime.h>
#include <string.h>

// Per-channel 5x5 correlation, stride=1, pad=2; 128 planes of 512x512 f32.
// R14 structure (register-buffered rolling + partial accsteps) + ONE change:
// prefetch.global.L2 of row s+6 each step (zero-register MLP: demand LDGs
// at depth-2 then hit L2 (~240cyc) instead of DRAM (~577cyc)).

#define IMG  512
#define R    16
#define NSTEP (R + 4)      // 20 input rows per strip
#define FULLMASK 0xffffffffu

typedef unsigned long long u64;

__device__ __forceinline__ u64 pk(float lo, float hi) {
    float2 t; t.x = lo; t.y = hi;
    u64 r; memcpy(&r, &t, 8);
    return r;
}
__device__ __forceinline__ u64 fma2(u64 a, u64 b, u64 c) {
    u64 d;
    asm("fma.rn.f32x2 %0, %1, %2, %3;" : "=l"(d) : "l"(a), "l"(b), "l"(c));
    return d;
}
__device__ __forceinline__ u64 mul2(u64 a, u64 b) {
    u64 d;
    asm("mul.rn.f32x2 %0, %1, %2;" : "=l"(d) : "l"(a), "l"(b));
    return d;
}

// Taps of input-row s (I = s mod 5) into pending output slots, restricted to
// kernel rows kr in [KRLO, KRHI]. Output o = s - kr lives in slot o % 5.
// kr==0 is an output's chronologically FIRST contribution: overwrite via mul.
template<int I, int KRLO, int KRHI>
__device__ __forceinline__ void accstep(u64 acc[5][4],
                                        const u64* __restrict__ wp,
                                        const u64* __restrict__ p) {
    #pragma unroll
    for (int kr = KRLO; kr <= KRHI; kr++) {
        const int slot = ((I - kr) % 5 + 5) % 5;
        #pragma unroll
        for (int t = 0; t < 5; t++) {
            #pragma unroll
            for (int pj = 0; pj < 4; pj++) {
                if (kr == 0 && t == 0)
                    acc[slot][pj] = mul2(wp[0], p[2 * pj]);
                else
                    acc[slot][pj] = fma2(wp[kr * 5 + t], p[2 * pj + t], acc[slot][pj]);
            }
        }
    }
}

__global__ __launch_bounds__(128, 5) void conv5x5_kernel(
    const float* __restrict__ X,
    const float* __restrict__ Kw,
    float* __restrict__ Out)
{
    const int lane  = threadIdx.x;
    const int wrp   = threadIdx.y;                  // 0..3
    const int c     = blockIdx.z;
    const int warpX = blockIdx.x;                   // 0..1
    const int strip = blockIdx.y * 4 + wrp;         // 0..31
    const int Y0    = strip * R;
    const int x0    = warpX * 256 + lane * 8;

    const float* __restrict__ Xc = X   + (size_t)c * (IMG * IMG);
    float*       __restrict__ Oc = Out + (size_t)c * (IMG * IMG);

    // packed (w,w) weights (warp-uniform -> UR promotion)
    u64 wp[25];
    #pragma unroll
    for (int i = 0; i < 25; i++) { const float wv = __ldg(&Kw[i]); wp[i] = pk(wv, wv); }

    u64 acc[5][4];
    #pragma unroll
    for (int j = 0; j < 5; j++)
        #pragma unroll
        for (int q = 0; q < 4; q++) acc[j][q] = 0ull;   // slots start via mul anyway

    u64 p[11];
    float4 Ab[2], Bb[2];      // double-buffered raw rows
    float2 LFb[2], RFb[2];

// L2 prefetch of input row S (main 8 floats only; halos ride on neighbors).
#define PREFROW(S) do {                                                        \
    const int gyp_ = Y0 - 2 + (S);                                             \
    if ((unsigned)gyp_ < (unsigned)IMG) {                                      \
        const float* pp_ = Xc + (size_t)gyp_ * IMG + x0;                       \
        asm volatile("prefetch.global.L2 [%0];" :: "l"(pp_));                  \
    }                                                                          \
} while (0)

// Load input row S into buffer PAR (zero outside image / past strip).
#define LOADROW(S, PAR) do {                                                   \
    const int s__ = (S);                                                       \
    const int gy_ = Y0 - 2 + s__;                                              \
    Ab[PAR] = make_float4(0.f,0.f,0.f,0.f); Bb[PAR] = make_float4(0.f,0.f,0.f,0.f); \
    LFb[PAR] = make_float2(0.f,0.f); RFb[PAR] = make_float2(0.f,0.f);          \
    if (s__ < NSTEP && (unsigned)gy_ < (unsigned)IMG) {                        \
        const float* rp_ = Xc + (size_t)gy_ * IMG + x0;                        \
        Ab[PAR] = *reinterpret_cast<const float4*>(rp_);                       \
        Bb[PAR] = *reinterpret_cast<const float4*>(rp_ + 4);                   \
        if (lane == 0  && x0 >= 2)      LFb[PAR] = *reinterpret_cast<const float2*>(rp_ - 2); \
        if (lane == 31 && x0 + 9 < IMG) RFb[PAR] = *reinterpret_cast<const float2*>(rp_ + 8); \
    }                                                                          \
} while (0)

// Shuffle halo + pack buffer PAR into p[0..10].
#define PACKROW(PAR) do {                                                      \
    float l0_ = __shfl_up_sync(FULLMASK,  Bb[PAR].z, 1);                       \
    float l1_ = __shfl_up_sync(FULLMASK,  Bb[PAR].w, 1);                       \
    float r0_ = __shfl_down_sync(FULLMASK, Ab[PAR].x, 1);                      \
    float r1_ = __shfl_down_sync(FULLMASK, Ab[PAR].y, 1);                      \
    if (lane == 0)  { l0_ = LFb[PAR].x; l1_ = LFb[PAR].y; }                    \
    if (lane == 31) { r0_ = RFb[PAR].x; r1_ = RFb[PAR].y; }                    \
    p[0]  = pk(l0_, l1_);             p[1]  = pk(l1_, Ab[PAR].x);              \
    p[2]  = pk(Ab[PAR].x, Ab[PAR].y); p[3]  = pk(Ab[PAR].y, Ab[PAR].z);        \
    p[4]  = pk(Ab[PAR].z, Ab[PAR].w); p[5]  = pk(Ab[PAR].w, Bb[PAR].x);        \
    p[6]  = pk(Bb[PAR].x, Bb[PAR].y); p[7]  = pk(Bb[PAR].y, Bb[PAR].z);        \
    p[8]  = pk(Bb[PAR].z, Bb[PAR].w); p[9]  = pk(Bb[PAR].w, r0_);              \
    p[10] = pk(r0_, r1_);                                                      \
} while (0)

#define STORE_ROW(S, SLOT) do {                                                \
    float* op_ = Oc + (size_t)(Y0 + (S) - 4) * IMG + x0;                       \
    *reinterpret_cast<ulonglong2*>(op_) =                                      \
        *reinterpret_cast<ulonglong2*>(&acc[SLOT][0]);                         \
    *reinterpret_cast<ulonglong2*>(op_ + 4) =                                  \
        *reinterpret_cast<ulonglong2*>(&acc[SLOT][2]);                         \
} while (0)

// Generic step, literal S and kr-range: prefetch row S+6 to L2; demand-load
// row S+2 into buf[S&1]; accumulate row S (in p); store output S-4; pack S+1.
#define GSTEP(S, KRLO, KRHI) do {                                              \
    LOADROW((S) + 2, (S) & 1);                                                 \
    PREFROW((S) + 6);                                                          \
    accstep<(S) % 5, KRLO, KRHI>(acc, wp, p);                                  \
    if ((S) >= 4) STORE_ROW((S), ((S)+1) % 5);                                 \
    if ((S) + 1 < NSTEP) PACKROW(((S) + 1) & 1);                               \
} while (0)

// Loop step: S = sb + J (sb even -> parity literal; sb % 5 == 4 -> slots literal).
#define LSTEP(J) do {                                                          \
    const int s_ = sb + (J);                                                   \
    LOADROW(s_ + 2, (J) & 1);                                                  \
    PREFROW(s_ + 6);                                                           \
    accstep<((J) + 4) % 5, 0, 4>(acc, wp, p);                                  \
    {                                                                          \
        float* op_ = Oc + (size_t)(Y0 + s_ - 4) * IMG + x0;                    \
        *reinterpret_cast<ulonglong2*>(op_) =                                  \
            *reinterpret_cast<ulonglong2*>(&acc[(J) % 5][0]);                  \
        *reinterpret_cast<ulonglong2*>(op_ + 4) =                              \
            *reinterpret_cast<ulonglong2*>(&acc[(J) % 5][2]);                  \
    }                                                                          \
    PACKROW(((J) + 1) & 1);                                                    \
} while (0)

    // prologue: L2-prefetch rows 2..5; demand rows 0,1; pack row 0
    PREFROW(2); PREFROW(3); PREFROW(4); PREFROW(5);
    LOADROW(0, 0);
    LOADROW(1, 1);
    PACKROW(0);

    // warm-up steps 0..3: only kr <= s feeds real outputs
    GSTEP(0, 0, 0);
    GSTEP(1, 0, 1);
    GSTEP(2, 0, 2);
    GSTEP(3, 0, 3);

    // full steps 4..13 (single unrolled 10-block; sb = 4 even -> parity literal)
    #pragma unroll 1
    for (int sb = 4; sb < 14; sb += 10) {
        LSTEP(0); LSTEP(1); LSTEP(2); LSTEP(3); LSTEP(4);
        LSTEP(5); LSTEP(6); LSTEP(7); LSTEP(8); LSTEP(9);
    }

    // full steps 14, 15
    GSTEP(14, 0, 4);
    GSTEP(15, 0, 4);

    // drain steps 16..19: only kr >= s-15 feeds real outputs
    GSTEP(16, 1, 4);
    GSTEP(17, 2, 4);
    GSTEP(18, 3, 4);
    GSTEP(19, 4, 4);

#undef LSTEP
#undef GSTEP
#undef STORE_ROW
#undef PACKROW
#undef LOADROW
#undef PREFROW
}

extern "C" void kernel_launch(void* const* d_in, const int* in_sizes, int n_in,
                              void* d_out, int out_size)
{
    const float* X  = (const float*)d_in[0];
    const float* Kw = (const float*)d_in[1];
    float* Out      = (float*)d_out;

    dim3 grid(2, IMG / R / 4, 128);   // 2 x-halves, 8 strip-groups, 128 planes = 2048 CTAs
    dim3 block(32, 4);                // 4 warps, each owns one 256x16 strip
    conv5x5_kernel<<<grid, block>>>(X, Kw, Out);
}